// round 13
// baseline (speedup 1.0000x reference)
#include <cuda_runtime.h>
#include <cstdint>

// ---------------------------------------------------------------------------
// Problem constants
#define B_       256
#define N_       131072
#define D_       256
#define TEMP_INV 20.0f        // 1 / 0.05

// int8 GEMM tiling
#define KP8     272           // smem row pitch in BYTES (17*16 -> 16B-aligned, conflict-free ldmatrix)
#define NTILE   64            // cluster rows per chunk
#define NCHUNKS (N_ / NTILE)  // 2048

// smem: A8[256][KP8] + B8[2][64][KP8]
#define SMEM_BYTES (B_ * KP8 + 2 * NTILE * KP8)   // 69632 + 34816 = 104448

// exp(logit) = exp2( acc_s32 * (TEMP_INV/(127*127)) * log2(e) )
#define C2 (TEMP_INV / 16129.0f * 1.44269504088896f)

__device__ float g_rowsum[B_];        // zero-init; self-zeroed by last CTA each run
__device__ float g_tlogit[B_];        // exact fp32 target logits
__device__ unsigned int g_arrive;     // zero-init; self-reset by last CTA

// ---------------------------------------------------------------------------
__device__ __forceinline__ uint32_t s2u(const void* p) {
    return (uint32_t)__cvta_generic_to_shared(p);
}

__device__ __forceinline__ void ldsm4(uint32_t* r, uint32_t a) {
    asm volatile("ldmatrix.sync.aligned.m8n8.x4.shared.b16 {%0,%1,%2,%3}, [%4];"
                 : "=r"(r[0]), "=r"(r[1]), "=r"(r[2]), "=r"(r[3]) : "r"(a));
}

__device__ __forceinline__ void imma(int* c, const uint32_t* a, uint32_t b0, uint32_t b1) {
    asm volatile(
        "mma.sync.aligned.m16n8k32.row.col.s32.s8.s8.s32 "
        "{%0,%1,%2,%3}, {%4,%5,%6,%7}, {%8,%9}, {%0,%1,%2,%3};"
        : "+r"(c[0]), "+r"(c[1]), "+r"(c[2]), "+r"(c[3])
        : "r"(a[0]), "r"(a[1]), "r"(a[2]), "r"(a[3]), "r"(b0), "r"(b1));
}

// quantize float4 (|v| <= 1) -> 4 packed s8 (scale 127)
__device__ __forceinline__ uint32_t q4(float4 v) {
    int q0 = __float2int_rn(v.x * 127.0f);
    int q1 = __float2int_rn(v.y * 127.0f);
    int q2 = __float2int_rn(v.z * 127.0f);
    int q3 = __float2int_rn(v.w * 127.0f);
    return (q0 & 0xff) | ((q1 & 0xff) << 8) | ((q2 & 0xff) << 16) | (q3 << 24);
}

// ---------------------------------------------------------------------------
// Single persistent fused kernel: int8 GEMM + exp row-sum + (last CTA) loss.
// 8 warps, warp grid 4(M) x 2(N): warp tile M=64, N=32 per chunk.
// B double-buffered in smem; next chunk register-prefetched during mma.
__global__ void __launch_bounds__(256, 1)
gemm_kernel(const float* __restrict__ inputs, const float* __restrict__ cluster,
            const int* __restrict__ indexes, const int* __restrict__ labels,
            float* __restrict__ out) {
    extern __shared__ char smem[];
    char* A8  = smem;                        // [256][KP8]
    char* B80 = smem + B_ * KP8;             // [64][KP8]
    char* B81 = B80 + NTILE * KP8;

    const int tid   = threadIdx.x;
    const int lane  = tid & 31;
    const int warp  = tid >> 5;
    const int wm    = warp & 3;       // m0 = wm*64
    const int wn    = warp >> 2;      // n_off = wn*32
    const int m0    = wm * 64;
    const int n_off = wn * 32;
    const int grid  = gridDim.x;

    // ---- register-stage first B chunk early (hide DRAM under prologue) ----
    const float4* cf4 = (const float4*)cluster;
    int c = blockIdx.x;
    float4 stage[16];
    {
        long base = (long)c * (NTILE * 64);
#pragma unroll
        for (int t = 0; t < 16; t++) stage[t] = cf4[base + tid + t * 256];
    }

    // ---- Convert A (inputs fp32 [256][256]) -> s8 smem, coalesced ----
    {
        const float4* in4 = (const float4*)inputs;
#pragma unroll
        for (int i = 0; i < 64; i++) {       // 16384 float4 / 256 thr
            int g   = tid + i * 256;
            int row = g >> 6;
            int c4  = g & 63;
            *(uint32_t*)(A8 + row * KP8 + c4 * 4) = q4(in4[g]);
        }
    }

    // ---- exact fp32 target logit for row r = bid + warp*grid (unique) ----
    {
        int r = blockIdx.x + warp * grid;
        if (r < B_) {
            int t = labels[indexes[r]];
            const float* a = inputs + r * D_;
            const float* b = cluster + (size_t)t * D_;
            float s = 0.0f;
#pragma unroll
            for (int k = lane; k < D_; k += 32) s = fmaf(a[k], b[k], s);
#pragma unroll
            for (int o = 16; o; o >>= 1) s += __shfl_xor_sync(0xffffffffu, s, o);
            if (lane == 0) g_tlogit[r] = s * TEMP_INV;
        }
    }

    // ---- ldmatrix lane-address bases (int8: 16B rows via b16 ldmatrix) ----
    uint32_t aAddr[4];
#pragma unroll
    for (int mi = 0; mi < 4; mi++) {
        int arow = m0 + mi * 16 + (lane & 15);
        aAddr[mi] = s2u(A8 + arow * KP8 + (lane >> 4) * 16);
    }
    uint32_t bOff[2];   // two n16 groups within warp's 32 N-columns
    {
        int koff = ((lane >> 3) & 1) * 16;
        int rsub = ((lane >> 4) << 3) + (lane & 7);
#pragma unroll
        for (int g = 0; g < 2; g++)
            bOff[g] = (uint32_t)((n_off + g * 16 + rsub) * KP8 + koff);
    }
    const uint32_t b0u = s2u(B80), b1u = s2u(B81);

    float sum0[4] = {0.f, 0.f, 0.f, 0.f};   // rows m0+mi*16+(lane>>2)
    float sum1[4] = {0.f, 0.f, 0.f, 0.f};   // rows +8

    __syncthreads();   // A visible

    int j = 0;
    for (; c < NCHUNKS; c += grid, j++) {
        const int p = j & 1;
        char* Bw = p ? B81 : B80;
        const uint32_t bBase = p ? b1u : b0u;

        // ---- store staged B chunk (fp32 regs -> s8 smem buffer p) ----
#pragma unroll
        for (int t = 0; t < 16; t++) {
            int g   = tid + t * 256;
            int row = g >> 6;                // 0..63
            int c4  = g & 63;
            *(uint32_t*)(Bw + row * KP8 + c4 * 4) = q4(stage[t]);
        }
        __syncthreads();   // B[p] visible; prior readers of B[p^1] done

        // ---- prefetch next chunk into registers (hidden under mma) ----
        if (c + grid < NCHUNKS) {
            long base = (long)(c + grid) * (NTILE * 64);
#pragma unroll
            for (int t = 0; t < 16; t++) stage[t] = cf4[base + tid + t * 256];
        }

        // ---- mma mainloop: warp tile M=64 x N=32, K=256 (8 k-steps of 32) ----
        int acc[4][4][4];
#pragma unroll
        for (int mi = 0; mi < 4; mi++)
#pragma unroll
            for (int ni = 0; ni < 4; ni++)
#pragma unroll
                for (int e = 0; e < 4; e++) acc[mi][ni][e] = 0;

#pragma unroll
        for (int kk = 0; kk < 8; kk++) {
            uint32_t a[4][4], b[2][4];
#pragma unroll
            for (int mi = 0; mi < 4; mi++) ldsm4(a[mi], aAddr[mi] + kk * 32);
#pragma unroll
            for (int g = 0; g < 2; g++)  ldsm4(b[g], bBase + bOff[g] + kk * 32);
#pragma unroll
            for (int mi = 0; mi < 4; mi++) {
                imma(acc[mi][0], a[mi], b[0][0], b[0][1]);
                imma(acc[mi][1], a[mi], b[0][2], b[0][3]);
                imma(acc[mi][2], a[mi], b[1][0], b[1][1]);
                imma(acc[mi][3], a[mi], b[1][2], b[1][3]);
            }
        }

        // ---- epilogue: exp2 + accumulate per-thread row partials ----
#pragma unroll
        for (int mi = 0; mi < 4; mi++) {
            float s0 = 0.f, s1 = 0.f;
#pragma unroll
            for (int ni = 0; ni < 4; ni++) {
                s0 += exp2f(__int2float_rn(acc[mi][ni][0]) * C2)
                    + exp2f(__int2float_rn(acc[mi][ni][1]) * C2);
                s1 += exp2f(__int2float_rn(acc[mi][ni][2]) * C2)
                    + exp2f(__int2float_rn(acc[mi][ni][3]) * C2);
            }
            sum0[mi] += s0;
            sum1[mi] += s1;
        }
    }

    // ---- reduce: quad shfl -> smem cross-warp (wn pair) -> atomicAdd ----
    __syncthreads();                       // done with B smem; reuse for reduce
    float* pbuf = (float*)B80;             // [2][256]
#pragma unroll
    for (int mi = 0; mi < 4; mi++) {
#pragma unroll
        for (int o = 1; o <= 2; o <<= 1) {
            sum0[mi] += __shfl_xor_sync(0xffffffffu, sum0[mi], o);
            sum1[mi] += __shfl_xor_sync(0xffffffffu, sum1[mi], o);
        }
        if ((lane & 3) == 0) {
            int r = m0 + mi * 16 + (lane >> 2);
            pbuf[wn * B_ + r]     = sum0[mi];
            pbuf[wn * B_ + r + 8] = sum1[mi];
        }
    }
    __syncthreads();
    if (tid < B_)
        atomicAdd(&g_rowsum[tid], pbuf[tid] + pbuf[B_ + tid]);

    // ---- last-arriving CTA computes the loss (threadfence reduction) ----
    __threadfence();
    __shared__ unsigned int ticket;
    if (tid == 0) ticket = atomicAdd(&g_arrive, 1u);
    __syncthreads();
    if (ticket == (unsigned)grid - 1u) {
        float* red = (float*)B80;          // reuse smem
        if (tid < B_) {
            float S = g_rowsum[tid];
            float p = expf(g_tlogit[tid]) / (S + 1e-6f);
            red[tid] = -logf(p + 1e-6f);
            g_rowsum[tid] = 0.0f;          // reset for next replay
        }
        if (tid == 0) g_arrive = 0u;       // reset counter
        __syncthreads();
#pragma unroll
        for (int s2 = 128; s2 > 0; s2 >>= 1) {
            if (tid < s2) red[tid] += red[tid + s2];
            __syncthreads();
        }
        if (tid == 0) out[0] = red[0] * (1.0f / (float)B_);
    }
}

// ---------------------------------------------------------------------------
extern "C" void kernel_launch(void* const* d_in, const int* in_sizes, int n_in,
                              void* d_out, int out_size) {
    const float* inputs  = (const float*)d_in[0];
    const float* cluster = (const float*)d_in[1];
    // d_in[2] = instance_features : unused by the loss
    const int* indexes = (const int*)d_in[3];
    const int* labels  = (const int*)d_in[4];
    float* out = (float*)d_out;

    int sms = 0;
    cudaDeviceGetAttribute(&sms, cudaDevAttrMultiProcessorCount, 0);
    if (sms <= 0) sms = 148;
    int grid = sms;
    if (grid > NCHUNKS) grid = NCHUNKS;

    cudaFuncSetAttribute(gemm_kernel,
                         cudaFuncAttributeMaxDynamicSharedMemorySize, SMEM_BYTES);

    gemm_kernel<<<grid, 256, SMEM_BYTES>>>(inputs, cluster, indexes, labels, out);
}

// round 14
// speedup vs baseline: 2.0699x; 2.0699x over previous
#include <cuda_runtime.h>
#include <cuda_bf16.h>
#include <cstdint>

// ---------------------------------------------------------------------------
// Problem constants
#define B_       256
#define N_       131072
#define D_       256
#define TEMP_INV 20.0f        // 1 / 0.05

// GEMM tiling (identical to the proven 73.9us R12 kernel's gemm)
#define KP      264           // smem row pitch in halfs (528 B = 33*16 -> 16B-aligned, conflict-free ldmatrix)
#define NTILE   64            // cluster rows per chunk
#define NCHUNKS (N_ / NTILE)  // 2048

// Shared memory (halfs): A[256][KP], B0[64][KP], B1[64][KP]
#define SMEM_HALFS (B_ * KP + 2 * NTILE * KP)
#define SMEM_BYTES (SMEM_HALFS * 2)          // 202752 B

__device__ float g_rowsum[B_];        // zero-init; self-zeroed by last CTA each run
__device__ float g_tlogit[B_];        // exact fp32 target logits
__device__ unsigned int g_arrive;     // zero-init; self-reset by last CTA

// ---------------------------------------------------------------------------
__device__ __forceinline__ uint32_t s2u(const void* p) {
    return (uint32_t)__cvta_generic_to_shared(p);
}

__device__ __forceinline__ void ldsm4(uint32_t* r, uint32_t a) {
    asm volatile("ldmatrix.sync.aligned.m8n8.x4.shared.b16 {%0,%1,%2,%3}, [%4];"
                 : "=r"(r[0]), "=r"(r[1]), "=r"(r[2]), "=r"(r[3]) : "r"(a));
}

__device__ __forceinline__ void mma_bf16(float* c, const uint32_t* a,
                                         uint32_t b0, uint32_t b1) {
    asm volatile(
        "mma.sync.aligned.m16n8k16.row.col.f32.bf16.bf16.f32 "
        "{%0,%1,%2,%3}, {%4,%5,%6,%7}, {%8,%9}, {%0,%1,%2,%3};"
        : "+f"(c[0]), "+f"(c[1]), "+f"(c[2]), "+f"(c[3])
        : "r"(a[0]), "r"(a[1]), "r"(a[2]), "r"(a[3]), "r"(b0), "r"(b1));
}

__device__ __forceinline__ uint32_t f2bf2(float lo, float hi) {
    uint32_t r;
    asm("{ .reg .b16 l, h;\n\t"
        "  cvt.rn.bf16.f32 l, %1;\n\t"
        "  cvt.rn.bf16.f32 h, %2;\n\t"
        "  mov.b32 %0, {l, h}; }"
        : "=r"(r) : "f"(lo), "f"(hi));
    return r;
}

// ---------------------------------------------------------------------------
// Single persistent fused kernel: bf16 GEMM + exp row-sum + (last CTA) loss.
// 8 warps, warp grid 4(M) x 2(N): warp tile M=64, N=32 per chunk.
// B double-buffered in smem; next chunk register-prefetched during mma.
__global__ void __launch_bounds__(256, 1)
gemm_kernel(const float* __restrict__ inputs, const float* __restrict__ cluster,
            const int* __restrict__ indexes, const int* __restrict__ labels,
            float* __restrict__ out) {
    extern __shared__ __nv_bfloat16 smem[];
    __nv_bfloat16* As  = smem;                       // [256][KP]
    __nv_bfloat16* Bs0 = smem + B_ * KP;             // [64][KP]
    __nv_bfloat16* Bs1 = Bs0 + NTILE * KP;           // [64][KP]

    const int tid   = threadIdx.x;
    const int lane  = tid & 31;
    const int warp  = tid >> 5;
    const int wm    = warp & 3;       // m0 = wm*64
    const int wn    = warp >> 2;      // n_off = wn*32
    const int m0    = wm * 64;
    const int n_off = wn * 32;
    const int grid  = gridDim.x;

    // ---- register-stage first B chunk early (hide DRAM under prologue) ----
    const float4* cf4 = (const float4*)cluster;
    int c = blockIdx.x;
    float4 stage[16];
    {
        long base = (long)c * (NTILE * 64);
#pragma unroll
        for (int t = 0; t < 16; t++) stage[t] = cf4[base + tid + t * 256];
    }

    // ---- Convert A (inputs fp32 [256][256]) -> bf16 smem, coalesced ----
    {
        const float4* in4 = (const float4*)inputs;
#pragma unroll
        for (int i = 0; i < 64; i++) {               // 16384 float4 / 256 thr
            int g   = tid + i * 256;
            int row = g >> 6;
            int c4  = g & 63;
            float4 v = in4[g];
            uint2 u; u.x = f2bf2(v.x, v.y); u.y = f2bf2(v.z, v.w);
            *(uint2*)(As + row * KP + c4 * 4) = u;
        }
    }

    // ---- exact fp32 target logit for row r = bid + warp*grid (unique) ----
    {
        int r = blockIdx.x + warp * grid;
        if (r < B_) {
            int t = labels[indexes[r]];
            const float* a = inputs + r * D_;
            const float* b = cluster + (size_t)t * D_;
            float s = 0.0f;
#pragma unroll
            for (int k = lane; k < D_; k += 32) s = fmaf(a[k], b[k], s);
#pragma unroll
            for (int o = 16; o; o >>= 1) s += __shfl_xor_sync(0xffffffffu, s, o);
            if (lane == 0) g_tlogit[r] = s * TEMP_INV;
        }
    }

    // ---- ldmatrix lane-address bases ----
    uint32_t aAddr[4];
#pragma unroll
    for (int mi = 0; mi < 4; mi++) {
        int arow = m0 + mi * 16 + (lane & 15);
        int acol = (lane >> 4) * 8;
        aAddr[mi] = s2u(As + arow * KP + acol);
    }
    // B base within a buffer (add buffer offset at use): two n16 groups (bp=0,1)
    uint32_t bOff[2];
    {
        int brow = n_off + (lane & 7) + ((lane >> 4) << 3);
        int bcol = ((lane >> 3) & 1) * 8;
        bOff[0] = (uint32_t)((brow * KP + bcol) * 2);
        bOff[1] = bOff[0] + 16 * KP * 2;
    }
    const uint32_t b0u = s2u(Bs0), b1u = s2u(Bs1);

    float sum0[4] = {0.f, 0.f, 0.f, 0.f};   // rows m0+mi*16+(lane>>2)
    float sum1[4] = {0.f, 0.f, 0.f, 0.f};   // rows +8

    __syncthreads();   // A visible

    int j = 0;
    for (; c < NCHUNKS; c += grid, j++) {
        const int p = j & 1;
        __nv_bfloat16* Bw = p ? Bs1 : Bs0;
        const uint32_t bBase = p ? b1u : b0u;

        // ---- store staged B chunk (fp32 regs -> bf16 smem buffer p) ----
#pragma unroll
        for (int t = 0; t < 16; t++) {
            int g   = tid + t * 256;
            int row = g >> 6;                        // 0..63
            int c4  = g & 63;
            float4 v = stage[t];
            uint2 u; u.x = f2bf2(v.x, v.y); u.y = f2bf2(v.z, v.w);
            *(uint2*)(Bw + row * KP + c4 * 4) = u;
        }
        __syncthreads();   // B[p] visible to all warps; B[p^1] readers (iter j-1) done

        // ---- prefetch next chunk into registers (hidden under mma) ----
        if (c + grid < NCHUNKS) {
            long base = (long)(c + grid) * (NTILE * 64);
#pragma unroll
            for (int t = 0; t < 16; t++) stage[t] = cf4[base + tid + t * 256];
        }

        // ---- mma mainloop: warp tile M=64 x N=32, K=256 ----
        float acc[4][4][4];
#pragma unroll
        for (int mi = 0; mi < 4; mi++)
#pragma unroll
            for (int ni = 0; ni < 4; ni++)
#pragma unroll
                for (int e = 0; e < 4; e++) acc[mi][ni][e] = 0.0f;

#pragma unroll
        for (int kk = 0; kk < 16; kk++) {
            uint32_t a[4][4], b[2][4];
#pragma unroll
            for (int mi = 0; mi < 4; mi++) ldsm4(a[mi], aAddr[mi] + kk * 32);
#pragma unroll
            for (int bp = 0; bp < 2; bp++) ldsm4(b[bp], bBase + bOff[bp] + kk * 32);
#pragma unroll
            for (int mi = 0; mi < 4; mi++) {
#pragma unroll
                for (int bp = 0; bp < 2; bp++) {
                    mma_bf16(acc[mi][2 * bp + 0], a[mi], b[bp][0], b[bp][1]);
                    mma_bf16(acc[mi][2 * bp + 1], a[mi], b[bp][2], b[bp][3]);
                }
            }
        }

        // ---- epilogue: exp + accumulate per-thread row partials ----
#pragma unroll
        for (int mi = 0; mi < 4; mi++) {
            float s0 = 0.f, s1 = 0.f;
#pragma unroll
            for (int ni = 0; ni < 4; ni++) {
                s0 += __expf(acc[mi][ni][0] * TEMP_INV) + __expf(acc[mi][ni][1] * TEMP_INV);
                s1 += __expf(acc[mi][ni][2] * TEMP_INV) + __expf(acc[mi][ni][3] * TEMP_INV);
            }
            sum0[mi] += s0;
            sum1[mi] += s1;
        }
    }

    // ---- reduce: quad shfl -> smem cross-warp (wn pair) -> atomicAdd ----
    __syncthreads();                       // done with Bs; reuse as reduce buffer
    float* pbuf = (float*)Bs0;             // [2][256]
#pragma unroll
    for (int mi = 0; mi < 4; mi++) {
#pragma unroll
        for (int o = 1; o <= 2; o <<= 1) {
            sum0[mi] += __shfl_xor_sync(0xffffffffu, sum0[mi], o);
            sum1[mi] += __shfl_xor_sync(0xffffffffu, sum1[mi], o);
        }
        if ((lane & 3) == 0) {
            int r = m0 + mi * 16 + (lane >> 2);
            pbuf[wn * B_ + r]     = sum0[mi];
            pbuf[wn * B_ + r + 8] = sum1[mi];
        }
    }
    __syncthreads();
    if (tid < B_)
        atomicAdd(&g_rowsum[tid], pbuf[tid] + pbuf[B_ + tid]);

    // ---- last-arriving CTA computes the loss (threadfence reduction) ----
    __threadfence();
    __shared__ unsigned int ticket;
    if (tid == 0) ticket = atomicAdd(&g_arrive, 1u);
    __syncthreads();
    if (ticket == (unsigned)grid - 1u) {
        float* red = (float*)Bs1;          // reuse smem (distinct from pbuf)
        if (tid < B_) {
            float S = g_rowsum[tid];
            float p = expf(g_tlogit[tid]) / (S + 1e-6f);
            red[tid] = -logf(p + 1e-6f);
            g_rowsum[tid] = 0.0f;          // reset for next graph replay
        }
        if (tid == 0) g_arrive = 0u;       // reset counter
        __syncthreads();
#pragma unroll
        for (int s2 = 128; s2 > 0; s2 >>= 1) {
            if (tid < s2) red[tid] += red[tid + s2];
            __syncthreads();
        }
        if (tid == 0) out[0] = red[0] * (1.0f / (float)B_);
    }
}

// ---------------------------------------------------------------------------
extern "C" void kernel_launch(void* const* d_in, const int* in_sizes, int n_in,
                              void* d_out, int out_size) {
    const float* inputs  = (const float*)d_in[0];
    const float* cluster = (const float*)d_in[1];
    // d_in[2] = instance_features : unused by the loss
    const int* indexes = (const int*)d_in[3];
    const int* labels  = (const int*)d_in[4];
    float* out = (float*)d_out;

    int sms = 0;
    cudaDeviceGetAttribute(&sms, cudaDevAttrMultiProcessorCount, 0);
    if (sms <= 0) sms = 148;
    int grid = sms;
    if (grid > NCHUNKS) grid = NCHUNKS;

    cudaFuncSetAttribute(gemm_kernel,
                         cudaFuncAttributeMaxDynamicSharedMemorySize, SMEM_BYTES);

    gemm_kernel<<<grid, 256, SMEM_BYTES>>>(inputs, cluster, indexes, labels, out);
}

// round 16
// speedup vs baseline: 2.2987x; 1.1105x over previous
#include <cuda_runtime.h>
#include <cuda_bf16.h>
#include <cstdint>

// ---------------------------------------------------------------------------
// Problem constants
#define B_       256
#define N_       131072
#define D_       256
#define TEMP_INV 20.0f        // 1 / 0.05

// GEMM tiling
#define KP      264           // smem row pitch in halfs (528 B = 33*16 -> 16B-aligned, conflict-free ldmatrix)
#define NTILE   64            // cluster rows per chunk
#define NCHUNKS (N_ / NTILE)  // 2048
#define NTHREADS 512          // 16 warps: warp grid 8(M) x 2(N), warp tile M=32 N=32

// Shared memory (halfs): A[256][KP], B0[64][KP], B1[64][KP]
#define SMEM_HALFS (B_ * KP + 2 * NTILE * KP)
#define SMEM_BYTES (SMEM_HALFS * 2)          // 202752 B

__device__ float g_rowsum[B_];        // zero-init; self-zeroed by last CTA each run
__device__ float g_tlogit[B_];        // exact fp32 target logits
__device__ unsigned int g_arrive;     // zero-init; self-reset by last CTA

// ---------------------------------------------------------------------------
__device__ __forceinline__ uint32_t s2u(const void* p) {
    return (uint32_t)__cvta_generic_to_shared(p);
}

__device__ __forceinline__ void ldsm4(uint32_t* r, uint32_t a) {
    asm volatile("ldmatrix.sync.aligned.m8n8.x4.shared.b16 {%0,%1,%2,%3}, [%4];"
                 : "=r"(r[0]), "=r"(r[1]), "=r"(r[2]), "=r"(r[3]) : "r"(a));
}

__device__ __forceinline__ void mma_bf16(float* c, const uint32_t* a,
                                         uint32_t b0, uint32_t b1) {
    asm volatile(
        "mma.sync.aligned.m16n8k16.row.col.f32.bf16.bf16.f32 "
        "{%0,%1,%2,%3}, {%4,%5,%6,%7}, {%8,%9}, {%0,%1,%2,%3};"
        : "+f"(c[0]), "+f"(c[1]), "+f"(c[2]), "+f"(c[3])
        : "r"(a[0]), "r"(a[1]), "r"(a[2]), "r"(a[3]), "r"(b0), "r"(b1));
}

__device__ __forceinline__ uint32_t f2bf2(float lo, float hi) {
    uint32_t r;
    asm("{ .reg .b16 l, h;\n\t"
        "  cvt.rn.bf16.f32 l, %1;\n\t"
        "  cvt.rn.bf16.f32 h, %2;\n\t"
        "  mov.b32 %0, {l, h}; }"
        : "=r"(r) : "f"(lo), "f"(hi));
    return r;
}

// ---------------------------------------------------------------------------
// Single persistent fused kernel: bf16 GEMM + exp row-sum + (last CTA) loss.
// 16 warps, warp grid 8(M) x 2(N): warp tile M=32, N=32 per chunk.
// B double-buffered in smem; next chunk register-prefetched during mma.
__global__ void __launch_bounds__(NTHREADS, 1)
gemm_kernel(const float* __restrict__ inputs, const float* __restrict__ cluster,
            const int* __restrict__ indexes, const int* __restrict__ labels,
            float* __restrict__ out) {
    extern __shared__ __nv_bfloat16 smem[];
    __nv_bfloat16* As  = smem;                       // [256][KP]
    __nv_bfloat16* Bs0 = smem + B_ * KP;             // [64][KP]
    __nv_bfloat16* Bs1 = Bs0 + NTILE * KP;           // [64][KP]

    const int tid   = threadIdx.x;
    const int lane  = tid & 31;
    const int warp  = tid >> 5;       // 0..15
    const int wm    = warp & 7;       // m0 = wm*32
    const int wn    = warp >> 3;      // n_off = wn*32
    const int m0    = wm * 32;
    const int n_off = wn * 32;
    const int grid  = gridDim.x;

    // ---- register-stage first B chunk early (hide DRAM under prologue) ----
    const float4* cf4 = (const float4*)cluster;
    int c = blockIdx.x;
    float4 stage[8];                  // 4096 float4 per chunk / 512 threads
    {
        long base = (long)c * (NTILE * 64);
#pragma unroll
        for (int t = 0; t < 8; t++) stage[t] = cf4[base + tid + t * NTHREADS];
    }

    // ---- Convert A (inputs fp32 [256][256]) -> bf16 smem, coalesced ----
    {
        const float4* in4 = (const float4*)inputs;
#pragma unroll
        for (int i = 0; i < 32; i++) {               // 16384 float4 / 512 thr
            int g   = tid + i * NTHREADS;
            int row = g >> 6;
            int c4  = g & 63;
            float4 v = in4[g];
            uint2 u; u.x = f2bf2(v.x, v.y); u.y = f2bf2(v.z, v.w);
            *(uint2*)(As + row * KP + c4 * 4) = u;
        }
    }

    // ---- exact fp32 target logit for row r = bid + warp*grid (unique) ----
    {
        int r = blockIdx.x + warp * grid;
        if (r < B_) {
            int t = labels[indexes[r]];
            const float* a = inputs + r * D_;
            const float* b = cluster + (size_t)t * D_;
            float s = 0.0f;
#pragma unroll
            for (int k = lane; k < D_; k += 32) s = fmaf(a[k], b[k], s);
#pragma unroll
            for (int o = 16; o; o >>= 1) s += __shfl_xor_sync(0xffffffffu, s, o);
            if (lane == 0) g_tlogit[r] = s * TEMP_INV;
        }
    }

    // ---- ldmatrix lane-address bases ----
    uint32_t aAddr[2];
#pragma unroll
    for (int mi = 0; mi < 2; mi++) {
        int arow = m0 + mi * 16 + (lane & 15);
        int acol = (lane >> 4) * 8;
        aAddr[mi] = s2u(As + arow * KP + acol);
    }
    // B base within a buffer (add buffer offset at use): two n16 groups (bp=0,1)
    uint32_t bOff[2];
    {
        int brow = n_off + (lane & 7) + ((lane >> 4) << 3);
        int bcol = ((lane >> 3) & 1) * 8;
        bOff[0] = (uint32_t)((brow * KP + bcol) * 2);
        bOff[1] = bOff[0] + 16 * KP * 2;
    }
    const uint32_t b0u = s2u(Bs0), b1u = s2u(Bs1);

    float sum0[2] = {0.f, 0.f};   // rows m0+mi*16+(lane>>2)
    float sum1[2] = {0.f, 0.f};   // rows +8

    __syncthreads();   // A visible

    int j = 0;
    for (; c < NCHUNKS; c += grid, j++) {
        const int p = j & 1;
        __nv_bfloat16* Bw = p ? Bs1 : Bs0;
        const uint32_t bBase = p ? b1u : b0u;

        // ---- store staged B chunk (fp32 regs -> bf16 smem buffer p) ----
#pragma unroll
        for (int t = 0; t < 8; t++) {
            int g   = tid + t * NTHREADS;
            int row = g >> 6;                        // 0..63
            int c4  = g & 63;
            float4 v = stage[t];
            uint2 u; u.x = f2bf2(v.x, v.y); u.y = f2bf2(v.z, v.w);
            *(uint2*)(Bw + row * KP + c4 * 4) = u;
        }
        __syncthreads();   // B[p] visible to all warps; B[p^1] readers (iter j-1) done

        // ---- prefetch next chunk into registers (hidden under mma) ----
        if (c + grid < NCHUNKS) {
            long base = (long)(c + grid) * (NTILE * 64);
#pragma unroll
            for (int t = 0; t < 8; t++) stage[t] = cf4[base + tid + t * NTHREADS];
        }

        // ---- mma mainloop: warp tile M=32 x N=32, K=256 ----
        float acc[2][4][4];
#pragma unroll
        for (int mi = 0; mi < 2; mi++)
#pragma unroll
            for (int ni = 0; ni < 4; ni++)
#pragma unroll
                for (int e = 0; e < 4; e++) acc[mi][ni][e] = 0.0f;

#pragma unroll
        for (int kk = 0; kk < 16; kk++) {
            uint32_t a[2][4], b[2][4];
#pragma unroll
            for (int mi = 0; mi < 2; mi++) ldsm4(a[mi], aAddr[mi] + kk * 32);
#pragma unroll
            for (int bp = 0; bp < 2; bp++) ldsm4(b[bp], bBase + bOff[bp] + kk * 32);
#pragma unroll
            for (int mi = 0; mi < 2; mi++) {
#pragma unroll
                for (int bp = 0; bp < 2; bp++) {
                    mma_bf16(acc[mi][2 * bp + 0], a[mi], b[bp][0], b[bp][1]);
                    mma_bf16(acc[mi][2 * bp + 1], a[mi], b[bp][2], b[bp][3]);
                }
            }
        }

        // ---- epilogue: exp + accumulate per-thread row partials ----
#pragma unroll
        for (int mi = 0; mi < 2; mi++) {
            float s0 = 0.f, s1 = 0.f;
#pragma unroll
            for (int ni = 0; ni < 4; ni++) {
                s0 += __expf(acc[mi][ni][0] * TEMP_INV) + __expf(acc[mi][ni][1] * TEMP_INV);
                s1 += __expf(acc[mi][ni][2] * TEMP_INV) + __expf(acc[mi][ni][3] * TEMP_INV);
            }
            sum0[mi] += s0;
            sum1[mi] += s1;
        }
    }

    // ---- reduce: quad shfl -> smem cross-warp (wn pair) -> atomicAdd ----
    __syncthreads();                       // done with Bs; reuse as reduce buffer
    float* pbuf = (float*)Bs0;             // [2][256]
#pragma unroll
    for (int mi = 0; mi < 2; mi++) {
#pragma unroll
        for (int o = 1; o <= 2; o <<= 1) {
            sum0[mi] += __shfl_xor_sync(0xffffffffu, sum0[mi], o);
            sum1[mi] += __shfl_xor_sync(0xffffffffu, sum1[mi], o);
        }
        if ((lane & 3) == 0) {
            int r = m0 + mi * 16 + (lane >> 2);
            pbuf[wn * B_ + r]     = sum0[mi];
            pbuf[wn * B_ + r + 8] = sum1[mi];
        }
    }
    __syncthreads();
    if (tid < B_)
        atomicAdd(&g_rowsum[tid], pbuf[tid] + pbuf[B_ + tid]);

    // ---- last-arriving CTA computes the loss (threadfence reduction) ----
    __threadfence();
    __shared__ unsigned int ticket;
    if (tid == 0) ticket = atomicAdd(&g_arrive, 1u);
    __syncthreads();
    if (ticket == (unsigned)grid - 1u) {
        float* red = (float*)Bs1;          // reuse smem (distinct from pbuf)
        if (tid < B_) {
            float S = g_rowsum[tid];
            float p = expf(g_tlogit[tid]) / (S + 1e-6f);
            red[tid] = -logf(p + 1e-6f);
            g_rowsum[tid] = 0.0f;          // reset for next graph replay
        }
        if (tid == 0) g_arrive = 0u;       // reset counter
        __syncthreads();
#pragma unroll
        for (int s2 = 128; s2 > 0; s2 >>= 1) {
            if (tid < s2) red[tid] += red[tid + s2];
            __syncthreads();
        }
        if (tid == 0) out[0] = red[0] * (1.0f / (float)B_);
    }
}

// ---------------------------------------------------------------------------
extern "C" void kernel_launch(void* const* d_in, const int* in_sizes, int n_in,
                              void* d_out, int out_size) {
    const float* inputs  = (const float*)d_in[0];
    const float* cluster = (const float*)d_in[1];
    // d_in[2] = instance_features : unused by the loss
    const int* indexes = (const int*)d_in[3];
    const int* labels  = (const int*)d_in[4];
    float* out = (float*)d_out;

    int sms = 0;
    cudaDeviceGetAttribute(&sms, cudaDevAttrMultiProcessorCount, 0);
    if (sms <= 0) sms = 148;
    int grid = sms;
    if (grid > NCHUNKS) grid = NCHUNKS;

    cudaFuncSetAttribute(gemm_kernel,
                         cudaFuncAttributeMaxDynamicSharedMemorySize, SMEM_BYTES);

    gemm_kernel<<<grid, NTHREADS, SMEM_BYTES>>>(inputs, cluster, indexes, labels, out);
}